// round 15
// baseline (speedup 1.0000x reference)
#include <cuda_runtime.h>
#include <cuda_fp16.h>
#include <math.h>
#include <stdint.h>

#define NU 100000
#define NI 100000
#define NE 300000
#define NROWS (NU + NI)
#define NPAD 200064            // 1563 * 128
#define MT 1563
#define G3 384
#define MDIM 512

__device__ int    d_lastU[NU];
__device__ int    d_lastV[NI];
__device__ __half d_X[(size_t)NPAD * MDIM];   // mail fp16 (padded rows stay 0)
__device__ __half d_H[(size_t)NPAD * 128];    // h fp16
__device__ __half d_hWi[G3 * MDIM];
__device__ __half d_hWh[G3 * 128];
__device__ __half d_G1[(size_t)NROWS * G3];
__device__ __half d_G2[(size_t)NROWS * G3];

// ---------------------------------------------------------------------------
__global__ void k_setup(const float* __restrict__ Wi, const float* __restrict__ Wh) {
    int i = blockIdx.x * blockDim.x + threadIdx.x;
    if (i < NU) d_lastU[i] = -1;
    if (i < NI) d_lastV[i] = -1;
    if (i < G3 * MDIM) d_hWi[i] = __float2half(Wi[i]);
    if (i < G3 * 128)  d_hWh[i] = __float2half(Wh[i]);
}

__global__ void k_scan_edges(const int* __restrict__ src, const int* __restrict__ dst) {
    int i = blockIdx.x * blockDim.x + threadIdx.x;
    if (i < NE) {
        atomicMax(&d_lastU[src[i]], i);
        atomicMax(&d_lastV[dst[i]], i);
    }
}

__device__ __forceinline__ uint32_t h2u(__half2 h) { return *(uint32_t*)&h; }

// build X rows (fp16, 8B stores) + H rows; 32 rows per 256-thr block.
__global__ void k_build_x(const float* __restrict__ si, const float* __restrict__ sj,
                          const float* __restrict__ t,  const float* __restrict__ efeat,
                          const int* __restrict__ src,  const int* __restrict__ dst,
                          const float* __restrict__ freq) {
    const int tid7  = threadIdx.x & 127;
    const int half_ = threadIdx.x >> 7;
    const int sec   = tid7 >> 5;
    const int c4    = (tid7 & 31) * 4;

    float4 fq = make_float4(0.f, 0.f, 0.f, 0.f);
    if (sec == 2) fq = __ldg((const float4*)(freq + c4));

#pragma unroll 1
    for (int i = 0; i < 16; ++i) {
        const int r = blockIdx.x * 32 + i * 2 + half_;

        int le;
        const float* ownbase;
        const float* otherArr;
        if (r < NU) {
            le = d_lastU[r];
            ownbase = si + (size_t)r * 128;
            otherArr = sj;
        } else {
            le = d_lastV[r - NU];
            ownbase = sj + (size_t)(r - NU) * 128;
            otherArr = si;
        }

        float4 v;
        if (sec == 1) {
            v = __ldg((const float4*)(ownbase + c4));
            uint2 hh;
            hh.x = h2u(__floats2half2_rn(v.x, v.y));
            hh.y = h2u(__floats2half2_rn(v.z, v.w));
            *(uint2*)(d_H + (size_t)r * 128 + c4) = hh;
            if (le < 0) v = make_float4(0.f, 0.f, 0.f, 0.f);
        } else if (le < 0) {
            v = make_float4(0.f, 0.f, 0.f, 0.f);
        } else if (sec == 0) {
            const int other = (r < NU) ? dst[le] : src[le];
            v = __ldg((const float4*)(otherArr + (size_t)other * 128 + c4));
        } else if (sec == 2) {
            const float tv = t[le];
            v.x = __cosf(tv * fq.x); v.y = __cosf(tv * fq.y);
            v.z = __cosf(tv * fq.z); v.w = __cosf(tv * fq.w);
        } else {
            v = __ldg((const float4*)(efeat + (size_t)le * 128 + c4));
        }

        uint2 p;
        p.x = h2u(__floats2half2_rn(v.x, v.y));
        p.y = h2u(__floats2half2_rn(v.z, v.w));
        *(uint2*)(d_X + (size_t)r * MDIM + sec * 128 + c4) = p;
    }
}

// ---------------------------------------------------------------------------
__device__ __forceinline__ uint32_t smem_u32(const void* p) {
    uint32_t a;
    asm("{ .reg .u64 t; cvta.to.shared.u64 t, %1; cvt.u32.u64 %0, t; }" : "=r"(a) : "l"(p));
    return a;
}
__device__ __forceinline__ void cp16cg(uint32_t dst, const void* src) {
    asm volatile("cp.async.cg.shared.global [%0], [%1], 16;"
                 :: "r"(dst), "l"(src) : "memory");
}
__device__ __forceinline__ void cp16ca(uint32_t dst, const void* src) {
    asm volatile("cp.async.ca.shared.global [%0], [%1], 16;"
                 :: "r"(dst), "l"(src) : "memory");
}
#define CP_COMMIT() asm volatile("cp.async.commit_group;" ::: "memory")
#define CP_WAIT3()  asm volatile("cp.async.wait_group 3;" ::: "memory")

__device__ __forceinline__ void ldsm4(uint32_t& r0, uint32_t& r1, uint32_t& r2,
                                      uint32_t& r3, uint32_t a) {
    asm volatile("ldmatrix.sync.aligned.m8n8.x4.shared.b16 {%0,%1,%2,%3}, [%4];"
                 : "=r"(r0), "=r"(r1), "=r"(r2), "=r"(r3) : "r"(a));
}
__device__ __forceinline__ void mma_f16(float c[4], uint32_t a0, uint32_t a1,
                                        uint32_t a2, uint32_t a3,
                                        uint32_t b0, uint32_t b1) {
    asm volatile(
        "mma.sync.aligned.m16n8k16.row.col.f32.f16.f16.f32 "
        "{%0,%1,%2,%3}, {%4,%5,%6,%7}, {%8,%9}, {%0,%1,%2,%3};"
        : "+f"(c[0]), "+f"(c[1]), "+f"(c[2]), "+f"(c[3])
        : "r"(a0), "r"(a1), "r"(a2), "r"(a3), "r"(b0), "r"(b1));
}

// fast sigmoid/tanh (ex2.approx + rcp.approx)
__device__ __forceinline__ float fsig(float x) {
    return __fdividef(1.f, 1.f + __expf(-x));
}
__device__ __forceinline__ float ftanh(float x) {
    return 2.f * fsig(2.f * x) - 1.f;
}

// swizzled byte offset within one [128 rows x 32 halves] 8KB chunk
__device__ __forceinline__ uint32_t sw_off(int m, int u) {
    return (uint32_t)((m << 6) + (((u ^ ((m >> 1) & 3)) & 3) << 4));
}

// ---------------------------------------------------------------------------
// Unified GEMM: 128x128 tile, BK=32, 5-stage cp.async (A .cg, B .ca),
// ldmatrix, warp tile 64x32 (2x4 warps), fp16 C store.
// blockIdx.y < MT -> G1 = X @ Wi^T (K=512); else G2 = H @ Wh^T (K=128).
#define STG_BYTES 16384
#define NSTG 5
#define SMEM_TOT  (NSTG * STG_BYTES)

__global__ __launch_bounds__(256, 2)
void k_hgemm(void) {
    extern __shared__ char smraw[];
    const uint32_t sb = smem_u32(smraw);

    const int ybid = blockIdx.y;
    const int sel  = (ybid >= MT) ? 1 : 0;
    const int my   = sel ? (ybid - MT) : ybid;

    const __half* A  = sel ? d_H   : d_X;
    const __half* Bw = sel ? d_hWh : d_hWi;
    const int K      = sel ? 128 : MDIM;
    __half* C        = sel ? d_G2 : d_G1;

    const int tid  = threadIdx.x;
    const int lane = tid & 31;
    const int w    = tid >> 5;
    const int wm   = w & 1;
    const int wn   = w >> 1;
    const int g    = lane >> 2;
    const int tg   = lane & 3;
    const int m0   = my * 128;
    const int n0   = blockIdx.x * 128;

    const int lrow = tid >> 1;
    const int u0   = (tid & 1) * 2;
    const __half* aP = A  + (size_t)(m0 + lrow) * K + u0 * 8;
    const __half* bP = Bw + (size_t)(n0 + lrow) * K + u0 * 8;
    const uint32_t dA0 = sw_off(lrow, u0);
    const uint32_t dA1 = sw_off(lrow, u0 + 1);

    uint32_t offA[4][2], offB[2][2];
    {
        const int mr = ((lane >> 3) & 1) * 8 + (lane & 7);
        const int uu = lane >> 4;
#pragma unroll
        for (int im = 0; im < 4; ++im)
#pragma unroll
            for (int kk = 0; kk < 2; ++kk)
                offA[im][kk] = sw_off(wm * 64 + im * 16 + mr, kk * 2 + uu);
#pragma unroll
        for (int j = 0; j < 2; ++j)
#pragma unroll
            for (int kk = 0; kk < 2; ++kk)
                offB[j][kk] = 8192u + sw_off(wn * 32 + j * 16 + mr, kk * 2 + uu);
    }

    float acc[4][4][4];
#pragma unroll
    for (int i = 0; i < 4; ++i)
#pragma unroll
        for (int j = 0; j < 4; ++j)
#pragma unroll
            for (int c = 0; c < 4; ++c) acc[i][j][c] = 0.f;

    const int nch = K >> 5;   // 16 or 4

    // prologue: 4 stages in flight
#pragma unroll
    for (int s = 0; s < 4; ++s) {
        const uint32_t st = sb + s * STG_BYTES;
        cp16cg(st + dA0,        aP + s * 32);
        cp16cg(st + dA1,        aP + s * 32 + 8);
        cp16ca(st + 8192 + dA0, bP + s * 32);
        cp16ca(st + 8192 + dA1, bP + s * 32 + 8);
        CP_COMMIT();
    }

    int rslot = 0, wslot = 4;
    for (int c = 0; c < nch; ++c) {
        CP_WAIT3();
        __syncthreads();

        if (c + 4 < nch) {
            const uint32_t st = sb + (uint32_t)wslot * STG_BYTES;
            cp16cg(st + dA0,        aP + (c + 4) * 32);
            cp16cg(st + dA1,        aP + (c + 4) * 32 + 8);
            cp16ca(st + 8192 + dA0, bP + (c + 4) * 32);
            cp16ca(st + 8192 + dA1, bP + (c + 4) * 32 + 8);
        }
        CP_COMMIT();

        const uint32_t stg = sb + (uint32_t)rslot * STG_BYTES;
#pragma unroll
        for (int kk = 0; kk < 2; ++kk) {
            uint32_t a[4][4], b[2][4];
#pragma unroll
            for (int im = 0; im < 4; ++im)
                ldsm4(a[im][0], a[im][1], a[im][2], a[im][3], stg + offA[im][kk]);
#pragma unroll
            for (int j = 0; j < 2; ++j)
                ldsm4(b[j][0], b[j][1], b[j][2], b[j][3], stg + offB[j][kk]);
#pragma unroll
            for (int im = 0; im < 4; ++im) {
                mma_f16(acc[im][0], a[im][0], a[im][1], a[im][2], a[im][3],
                        b[0][0], b[0][2]);
                mma_f16(acc[im][1], a[im][0], a[im][1], a[im][2], a[im][3],
                        b[0][1], b[0][3]);
                mma_f16(acc[im][2], a[im][0], a[im][1], a[im][2], a[im][3],
                        b[1][0], b[1][2]);
                mma_f16(acc[im][3], a[im][0], a[im][1], a[im][2], a[im][3],
                        b[1][1], b[1][3]);
            }
        }
        if (++rslot == NSTG) rslot = 0;
        if (++wslot == NSTG) wslot = 0;
    }

    // epilogue: fp16 store
#pragma unroll
    for (int im = 0; im < 4; ++im) {
#pragma unroll
        for (int in_ = 0; in_ < 4; ++in_) {
            const int row = m0 + wm * 64 + im * 16 + g;
            const int col = n0 + wn * 32 + in_ * 8 + tg * 2;
            if (row < NROWS)
                *(__half2*)(C + (size_t)row * G3 + col) =
                    __floats2half2_rn(acc[im][in_][0], acc[im][in_][1]);
            if (row + 8 < NROWS)
                *(__half2*)(C + (size_t)(row + 8) * G3 + col) =
                    __floats2half2_rn(acc[im][in_][2], acc[im][in_][3]);
        }
    }
}

// ---------------------------------------------------------------------------
__device__ __forceinline__ float2 ldh2(const __half* p) {
    return __half22float2(*(const __half2*)p);
}

// Combine: 32 rows per 256-thr block; biases hoisted; fast activations.
__global__ void k_combine(const float* __restrict__ si, const float* __restrict__ sj,
                          const float* __restrict__ bi, const float* __restrict__ bh,
                          float* __restrict__ out) {
    const int sub = threadIdx.x >> 6;
    const int j   = (threadIdx.x & 63) * 2;

    const float2 bir = __ldg((const float2*)(bi + j));
    const float2 biz = __ldg((const float2*)(bi + 128 + j));
    const float2 bin = __ldg((const float2*)(bi + 256 + j));
    const float2 bhr = __ldg((const float2*)(bh + j));
    const float2 bhz = __ldg((const float2*)(bh + 128 + j));
    const float2 bhn = __ldg((const float2*)(bh + 256 + j));

#pragma unroll 1
    for (int i = 0; i < 8; ++i) {
        const int r = blockIdx.x * 32 + i * 4 + sub;

        const __half* g1 = d_G1 + (size_t)r * G3;
        const __half* g2 = d_G2 + (size_t)r * G3;
        const float* hp = (r < NU) ? si + (size_t)r * 128
                                   : sj + (size_t)(r - NU) * 128;

        float2 g1r = ldh2(g1 + j);
        float2 g1z = ldh2(g1 + 128 + j);
        float2 g1n = ldh2(g1 + 256 + j);
        float2 g2r = ldh2(g2 + j);
        float2 g2z = ldh2(g2 + 128 + j);
        float2 g2n = ldh2(g2 + 256 + j);
        float2 hv  = *(const float2*)(hp + j);

        float r0 = fsig(g1r.x + bir.x + g2r.x + bhr.x);
        float r1 = fsig(g1r.y + bir.y + g2r.y + bhr.y);
        float z0 = fsig(g1z.x + biz.x + g2z.x + bhz.x);
        float z1 = fsig(g1z.y + biz.y + g2z.y + bhz.y);
        float n0 = ftanh(g1n.x + bin.x + r0 * (g2n.x + bhn.x));
        float n1 = ftanh(g1n.y + bin.y + r1 * (g2n.y + bhn.y));

        float2 o;
        o.x = (1.f - z0) * n0 + z0 * hv.x;
        o.y = (1.f - z1) * n1 + z1 * hv.y;
        *(float2*)(out + (size_t)r * 128 + j) = o;
    }
}

// ---------------------------------------------------------------------------
extern "C" void kernel_launch(void* const* d_in, const int* in_sizes, int n_in,
                              void* d_out, int out_size) {
    const float* si   = (const float*)d_in[0];
    const float* sj   = (const float*)d_in[1];
    const float* t    = (const float*)d_in[2];
    const float* ef   = (const float*)d_in[3];
    const int*   src  = (const int*)d_in[4];
    const int*   dst  = (const int*)d_in[5];
    const float* Wi   = (const float*)d_in[6];
    const float* Wh   = (const float*)d_in[7];
    const float* bi   = (const float*)d_in[8];
    const float* bh   = (const float*)d_in[9];
    const float* freq = (const float*)d_in[10];
    float* out = (float*)d_out;

    k_setup<<<(G3 * MDIM + 255) / 256, 256>>>(Wi, Wh);
    k_scan_edges<<<(NE + 255) / 256, 256>>>(src, dst);
    k_build_x<<<NROWS / 32, 256>>>(si, sj, t, ef, src, dst, freq);

    cudaFuncSetAttribute(k_hgemm, cudaFuncAttributeMaxDynamicSharedMemorySize, SMEM_TOT);
    dim3 grid(3, 2 * MT);
    k_hgemm<<<grid, 256, SMEM_TOT>>>();

    k_combine<<<NROWS / 32, 256>>>(si, sj, bi, bh, out);
}

// round 16
// speedup vs baseline: 1.0672x; 1.0672x over previous
#include <cuda_runtime.h>
#include <cuda_fp16.h>
#include <math.h>
#include <stdint.h>

#define NU 100000
#define NI 100000
#define NE 300000
#define NROWS (NU + NI)
#define NPAD 200064            // 1563 * 128
#define MT 1563
#define G3 384
#define MDIM 512

__device__ int    d_lastU[NU];
__device__ int    d_lastV[NI];
__device__ __half d_X[(size_t)NPAD * MDIM];   // mail fp16 (padded rows stay 0)
__device__ __half d_H[(size_t)NPAD * 128];    // h fp16
__device__ __half d_hWi[G3 * MDIM];
__device__ __half d_hWh[G3 * 128];
__device__ __half d_G1[(size_t)NROWS * G3];
__device__ __half d_G2[(size_t)NROWS * G3];

// ---------------------------------------------------------------------------
__global__ void k_setup(const float* __restrict__ Wi, const float* __restrict__ Wh) {
    int i = blockIdx.x * blockDim.x + threadIdx.x;
    if (i < NU) d_lastU[i] = -1;
    if (i < NI) d_lastV[i] = -1;
    if (i < G3 * MDIM) d_hWi[i] = __float2half(Wi[i]);
    if (i < G3 * 128)  d_hWh[i] = __float2half(Wh[i]);
}

__global__ void k_scan_edges(const int* __restrict__ src, const int* __restrict__ dst) {
    int i = blockIdx.x * blockDim.x + threadIdx.x;
    if (i < NE) {
        atomicMax(&d_lastU[src[i]], i);
        atomicMax(&d_lastV[dst[i]], i);
    }
}

__device__ __forceinline__ uint32_t h2u(__half2 h) { return *(uint32_t*)&h; }

// build X rows (fp16, 8B stores) + H rows; 32 rows per 256-thr block.
__global__ void k_build_x(const float* __restrict__ si, const float* __restrict__ sj,
                          const float* __restrict__ t,  const float* __restrict__ efeat,
                          const int* __restrict__ src,  const int* __restrict__ dst,
                          const float* __restrict__ freq) {
    const int tid7  = threadIdx.x & 127;
    const int half_ = threadIdx.x >> 7;
    const int sec   = tid7 >> 5;
    const int c4    = (tid7 & 31) * 4;

    float4 fq = make_float4(0.f, 0.f, 0.f, 0.f);
    if (sec == 2) fq = __ldg((const float4*)(freq + c4));

#pragma unroll 1
    for (int i = 0; i < 16; ++i) {
        const int r = blockIdx.x * 32 + i * 2 + half_;

        int le;
        const float* ownbase;
        const float* otherArr;
        if (r < NU) {
            le = d_lastU[r];
            ownbase = si + (size_t)r * 128;
            otherArr = sj;
        } else {
            le = d_lastV[r - NU];
            ownbase = sj + (size_t)(r - NU) * 128;
            otherArr = si;
        }

        float4 v;
        if (sec == 1) {
            v = __ldg((const float4*)(ownbase + c4));
            uint2 hh;
            hh.x = h2u(__floats2half2_rn(v.x, v.y));
            hh.y = h2u(__floats2half2_rn(v.z, v.w));
            *(uint2*)(d_H + (size_t)r * 128 + c4) = hh;
            if (le < 0) v = make_float4(0.f, 0.f, 0.f, 0.f);
        } else if (le < 0) {
            v = make_float4(0.f, 0.f, 0.f, 0.f);
        } else if (sec == 0) {
            const int other = (r < NU) ? dst[le] : src[le];
            v = __ldg((const float4*)(otherArr + (size_t)other * 128 + c4));
        } else if (sec == 2) {
            const float tv = t[le];
            v.x = __cosf(tv * fq.x); v.y = __cosf(tv * fq.y);
            v.z = __cosf(tv * fq.z); v.w = __cosf(tv * fq.w);
        } else {
            v = __ldg((const float4*)(efeat + (size_t)le * 128 + c4));
        }

        uint2 p;
        p.x = h2u(__floats2half2_rn(v.x, v.y));
        p.y = h2u(__floats2half2_rn(v.z, v.w));
        *(uint2*)(d_X + (size_t)r * MDIM + sec * 128 + c4) = p;
    }
}

// ---------------------------------------------------------------------------
__device__ __forceinline__ uint32_t smem_u32(const void* p) {
    uint32_t a;
    asm("{ .reg .u64 t; cvta.to.shared.u64 t, %1; cvt.u32.u64 %0, t; }" : "=r"(a) : "l"(p));
    return a;
}
__device__ __forceinline__ void cp16(uint32_t dst, const void* src) {
    asm volatile("cp.async.cg.shared.global [%0], [%1], 16;"
                 :: "r"(dst), "l"(src) : "memory");
}
#define CP_COMMIT() asm volatile("cp.async.commit_group;" ::: "memory")
#define CP_WAIT2()  asm volatile("cp.async.wait_group 2;" ::: "memory")

__device__ __forceinline__ void ldsm4(uint32_t& r0, uint32_t& r1, uint32_t& r2,
                                      uint32_t& r3, uint32_t a) {
    asm volatile("ldmatrix.sync.aligned.m8n8.x4.shared.b16 {%0,%1,%2,%3}, [%4];"
                 : "=r"(r0), "=r"(r1), "=r"(r2), "=r"(r3) : "r"(a));
}
__device__ __forceinline__ void mma_f16(float c[4], uint32_t a0, uint32_t a1,
                                        uint32_t a2, uint32_t a3,
                                        uint32_t b0, uint32_t b1) {
    asm volatile(
        "mma.sync.aligned.m16n8k16.row.col.f32.f16.f16.f32 "
        "{%0,%1,%2,%3}, {%4,%5,%6,%7}, {%8,%9}, {%0,%1,%2,%3};"
        : "+f"(c[0]), "+f"(c[1]), "+f"(c[2]), "+f"(c[3])
        : "r"(a0), "r"(a1), "r"(a2), "r"(a3), "r"(b0), "r"(b1));
}

// fast sigmoid/tanh (ex2.approx + rcp.approx)
__device__ __forceinline__ float fsig(float x) {
    return __fdividef(1.f, 1.f + __expf(-x));
}
__device__ __forceinline__ float ftanh(float x) {
    return 2.f * fsig(2.f * x) - 1.f;
}

// swizzled byte offset within one [128 rows x 32 halves] 8KB chunk
__device__ __forceinline__ uint32_t sw_off(int m, int u) {
    return (uint32_t)((m << 6) + (((u ^ ((m >> 1) & 3)) & 3) << 4));
}

// ---------------------------------------------------------------------------
// Unified GEMM (R14-proven): 128x128 tile, BK=32, 4-stage cp.async (.cg),
// ldmatrix, warp tile 64x32 (2x4 warps), fp16 C store.
// blockIdx.y < MT -> G1 = X @ Wi^T (K=512); else G2 = H @ Wh^T (K=128).
#define STG_BYTES 16384
#define SMEM_TOT  (4 * STG_BYTES)

__global__ __launch_bounds__(256, 2)
void k_hgemm(void) {
    extern __shared__ char smraw[];
    const uint32_t sb = smem_u32(smraw);

    const int ybid = blockIdx.y;
    const int sel  = (ybid >= MT) ? 1 : 0;
    const int my   = sel ? (ybid - MT) : ybid;

    const __half* A  = sel ? d_H   : d_X;
    const __half* Bw = sel ? d_hWh : d_hWi;
    const int K      = sel ? 128 : MDIM;
    __half* C        = sel ? d_G2 : d_G1;

    const int tid  = threadIdx.x;
    const int lane = tid & 31;
    const int w    = tid >> 5;
    const int wm   = w & 1;
    const int wn   = w >> 1;
    const int g    = lane >> 2;
    const int tg   = lane & 3;
    const int m0   = my * 128;
    const int n0   = blockIdx.x * 128;

    const int lrow = tid >> 1;
    const int u0   = (tid & 1) * 2;
    const __half* aP = A  + (size_t)(m0 + lrow) * K + u0 * 8;
    const __half* bP = Bw + (size_t)(n0 + lrow) * K + u0 * 8;
    const uint32_t dA0 = sw_off(lrow, u0);
    const uint32_t dA1 = sw_off(lrow, u0 + 1);

    uint32_t offA[4][2], offB[2][2];
    {
        const int mr = ((lane >> 3) & 1) * 8 + (lane & 7);
        const int uu = lane >> 4;
#pragma unroll
        for (int im = 0; im < 4; ++im)
#pragma unroll
            for (int kk = 0; kk < 2; ++kk)
                offA[im][kk] = sw_off(wm * 64 + im * 16 + mr, kk * 2 + uu);
#pragma unroll
        for (int j = 0; j < 2; ++j)
#pragma unroll
            for (int kk = 0; kk < 2; ++kk)
                offB[j][kk] = 8192u + sw_off(wn * 32 + j * 16 + mr, kk * 2 + uu);
    }

    float acc[4][4][4];
#pragma unroll
    for (int i = 0; i < 4; ++i)
#pragma unroll
        for (int j = 0; j < 4; ++j)
#pragma unroll
            for (int c = 0; c < 4; ++c) acc[i][j][c] = 0.f;

    const int nch = K >> 5;   // 16 or 4

#pragma unroll
    for (int s = 0; s < 3; ++s) {
        const uint32_t st = sb + s * STG_BYTES;
        cp16(st + dA0,        aP + s * 32);
        cp16(st + dA1,        aP + s * 32 + 8);
        cp16(st + 8192 + dA0, bP + s * 32);
        cp16(st + 8192 + dA1, bP + s * 32 + 8);
        CP_COMMIT();
    }

    for (int c = 0; c < nch; ++c) {
        CP_WAIT2();
        __syncthreads();

        if (c + 3 < nch) {
            const uint32_t st = sb + ((c + 3) & 3) * STG_BYTES;
            cp16(st + dA0,        aP + (c + 3) * 32);
            cp16(st + dA1,        aP + (c + 3) * 32 + 8);
            cp16(st + 8192 + dA0, bP + (c + 3) * 32);
            cp16(st + 8192 + dA1, bP + (c + 3) * 32 + 8);
        }
        CP_COMMIT();

        const uint32_t stg = sb + (c & 3) * STG_BYTES;
#pragma unroll
        for (int kk = 0; kk < 2; ++kk) {
            uint32_t a[4][4], b[2][4];
#pragma unroll
            for (int im = 0; im < 4; ++im)
                ldsm4(a[im][0], a[im][1], a[im][2], a[im][3], stg + offA[im][kk]);
#pragma unroll
            for (int j = 0; j < 2; ++j)
                ldsm4(b[j][0], b[j][1], b[j][2], b[j][3], stg + offB[j][kk]);
#pragma unroll
            for (int im = 0; im < 4; ++im) {
                mma_f16(acc[im][0], a[im][0], a[im][1], a[im][2], a[im][3],
                        b[0][0], b[0][2]);
                mma_f16(acc[im][1], a[im][0], a[im][1], a[im][2], a[im][3],
                        b[0][1], b[0][3]);
                mma_f16(acc[im][2], a[im][0], a[im][1], a[im][2], a[im][3],
                        b[1][0], b[1][2]);
                mma_f16(acc[im][3], a[im][0], a[im][1], a[im][2], a[im][3],
                        b[1][1], b[1][3]);
            }
        }
    }

#pragma unroll
    for (int im = 0; im < 4; ++im) {
#pragma unroll
        for (int in_ = 0; in_ < 4; ++in_) {
            const int row = m0 + wm * 64 + im * 16 + g;
            const int col = n0 + wn * 32 + in_ * 8 + tg * 2;
            if (row < NROWS)
                *(__half2*)(C + (size_t)row * G3 + col) =
                    __floats2half2_rn(acc[im][in_][0], acc[im][in_][1]);
            if (row + 8 < NROWS)
                *(__half2*)(C + (size_t)(row + 8) * G3 + col) =
                    __floats2half2_rn(acc[im][in_][2], acc[im][in_][3]);
        }
    }
}

// ---------------------------------------------------------------------------
__device__ __forceinline__ float2 ldh2(const __half* p) {
    return __half22float2(*(const __half2*)p);
}

// Combine: 32 rows per 256-thr block; biases hoisted; fast activations;
// h loaded from d_H (fp16, L2-warm) instead of si/sj (fp32).
__global__ void k_combine(const float* __restrict__ bi, const float* __restrict__ bh,
                          float* __restrict__ out) {
    const int sub = threadIdx.x >> 6;
    const int j   = (threadIdx.x & 63) * 2;

    const float2 bir = __ldg((const float2*)(bi + j));
    const float2 biz = __ldg((const float2*)(bi + 128 + j));
    const float2 bin = __ldg((const float2*)(bi + 256 + j));
    const float2 bhr = __ldg((const float2*)(bh + j));
    const float2 bhz = __ldg((const float2*)(bh + 128 + j));
    const float2 bhn = __ldg((const float2*)(bh + 256 + j));

#pragma unroll 1
    for (int i = 0; i < 8; ++i) {
        const int r = blockIdx.x * 32 + i * 4 + sub;

        const __half* g1 = d_G1 + (size_t)r * G3;
        const __half* g2 = d_G2 + (size_t)r * G3;

        float2 g1r = ldh2(g1 + j);
        float2 g1z = ldh2(g1 + 128 + j);
        float2 g1n = ldh2(g1 + 256 + j);
        float2 g2r = ldh2(g2 + j);
        float2 g2z = ldh2(g2 + 128 + j);
        float2 g2n = ldh2(g2 + 256 + j);
        float2 hv  = ldh2(d_H + (size_t)r * 128 + j);

        float r0 = fsig(g1r.x + bir.x + g2r.x + bhr.x);
        float r1 = fsig(g1r.y + bir.y + g2r.y + bhr.y);
        float z0 = fsig(g1z.x + biz.x + g2z.x + bhz.x);
        float z1 = fsig(g1z.y + biz.y + g2z.y + bhz.y);
        float n0 = ftanh(g1n.x + bin.x + r0 * (g2n.x + bhn.x));
        float n1 = ftanh(g1n.y + bin.y + r1 * (g2n.y + bhn.y));

        float2 o;
        o.x = (1.f - z0) * n0 + z0 * hv.x;
        o.y = (1.f - z1) * n1 + z1 * hv.y;
        *(float2*)(out + (size_t)r * 128 + j) = o;
    }
}

// ---------------------------------------------------------------------------
extern "C" void kernel_launch(void* const* d_in, const int* in_sizes, int n_in,
                              void* d_out, int out_size) {
    const float* si   = (const float*)d_in[0];
    const float* sj   = (const float*)d_in[1];
    const float* t    = (const float*)d_in[2];
    const float* ef   = (const float*)d_in[3];
    const int*   src  = (const int*)d_in[4];
    const int*   dst  = (const int*)d_in[5];
    const float* Wi   = (const float*)d_in[6];
    const float* Wh   = (const float*)d_in[7];
    const float* bi   = (const float*)d_in[8];
    const float* bh   = (const float*)d_in[9];
    const float* freq = (const float*)d_in[10];
    float* out = (float*)d_out;

    k_setup<<<(G3 * MDIM + 255) / 256, 256>>>(Wi, Wh);
    k_scan_edges<<<(NE + 255) / 256, 256>>>(src, dst);
    k_build_x<<<NROWS / 32, 256>>>(si, sj, t, ef, src, dst, freq);

    cudaFuncSetAttribute(k_hgemm, cudaFuncAttributeMaxDynamicSharedMemorySize, SMEM_TOT);
    dim3 grid(3, 2 * MT);
    k_hgemm<<<grid, 256, SMEM_TOT>>>();

    k_combine<<<NROWS / 32, 256>>>(bi, bh, out);
}